// round 2
// baseline (speedup 1.0000x reference)
#include <cuda_runtime.h>
#include <cuda_bf16.h>

#define BB 2
#define TT 2048
#define DD 1024
#define HH 16
#define DKK 64
#define BT 4096   // BB*TT

// ---------------- scratch (device globals; no runtime allocation) -------------
__device__ float g_q[(size_t)BT * DD];
__device__ float g_k[(size_t)BT * DD];
__device__ float g_v[(size_t)BT * DD];
__device__ float g_x[(size_t)BT * DD];
__device__ float g_o[(size_t)BT * DD];
// fallback attn scratch in case d_out only holds y (tuple handling safety)
__device__ float g_attn_scratch[(size_t)BB * HH * TT * TT];

// =============================================================================
// Generic NT SGEMM:  C[m,n] = alpha * sum_k A[m,k]*Bm[n,k]  (+ bias[n])
// Batched over blockIdx.z: per-z offsets  (z>>4)*s?b + (z&15)*s?h  for A and B,
// linear z*sCz for C. 128x128 tile, BK=8, 256 threads, 8x8 per-thread tile.
// All problem dims here divide the tiles exactly, so no bounds checks.
// =============================================================================
__global__ __launch_bounds__(256)
void sgemm_nt(const float* __restrict__ A, int lda, long sAb, long sAh,
              const float* __restrict__ Bm, int ldb, long sBb, long sBh,
              float* __restrict__ C, int ldc, long sCz,
              const float* __restrict__ bias, int K, float alpha)
{
    __shared__ float As[8][128];
    __shared__ float Bs[8][128];

    int z = blockIdx.z;
    A  += (long)(z >> 4) * sAb + (long)(z & 15) * sAh;
    Bm += (long)(z >> 4) * sBb + (long)(z & 15) * sBh;
    C  += (long)z * sCz;

    int tid = threadIdx.x;
    int bm = blockIdx.y * 128;
    int bn = blockIdx.x * 128;

    int lrow = tid >> 1;          // 0..127
    int lcol = (tid & 1) * 4;     // 0 or 4

    const float* Ap = A  + (long)(bm + lrow) * lda + lcol;
    const float* Bp = Bm + (long)(bn + lrow) * ldb + lcol;

    int tr = (tid >> 4) * 8;      // 0..120
    int tc = (tid & 15) * 8;      // 0..120

    float acc[8][8];
#pragma unroll
    for (int i = 0; i < 8; i++)
#pragma unroll
        for (int j = 0; j < 8; j++) acc[i][j] = 0.0f;

    for (int k0 = 0; k0 < K; k0 += 8) {
        float4 av = *(const float4*)(Ap + k0);
        float4 bv = *(const float4*)(Bp + k0);
        As[lcol + 0][lrow] = av.x; As[lcol + 1][lrow] = av.y;
        As[lcol + 2][lrow] = av.z; As[lcol + 3][lrow] = av.w;
        Bs[lcol + 0][lrow] = bv.x; Bs[lcol + 1][lrow] = bv.y;
        Bs[lcol + 2][lrow] = bv.z; Bs[lcol + 3][lrow] = bv.w;
        __syncthreads();
#pragma unroll
        for (int k = 0; k < 8; k++) {
            float af[8], bf[8];
            *(float4*)(af)     = *(const float4*)(&As[k][tr]);
            *(float4*)(af + 4) = *(const float4*)(&As[k][tr + 4]);
            *(float4*)(bf)     = *(const float4*)(&Bs[k][tc]);
            *(float4*)(bf + 4) = *(const float4*)(&Bs[k][tc + 4]);
#pragma unroll
            for (int i = 0; i < 8; i++)
#pragma unroll
                for (int j = 0; j < 8; j++)
                    acc[i][j] = fmaf(af[i], bf[j], acc[i][j]);
        }
        __syncthreads();
    }

    float bvals[8];
#pragma unroll
    for (int j = 0; j < 8; j++)
        bvals[j] = bias ? bias[bn + tc + j] : 0.0f;

#pragma unroll
    for (int i = 0; i < 8; i++) {
        long crow = (long)(bm + tr + i) * ldc + bn + tc;
#pragma unroll
        for (int j4 = 0; j4 < 2; j4++) {
            float4 o;
            o.x = alpha * acc[i][j4 * 4 + 0] + bvals[j4 * 4 + 0];
            o.y = alpha * acc[i][j4 * 4 + 1] + bvals[j4 * 4 + 1];
            o.z = alpha * acc[i][j4 * 4 + 2] + bvals[j4 * 4 + 2];
            o.w = alpha * acc[i][j4 * 4 + 3] + bvals[j4 * 4 + 3];
            *(float4*)(C + crow + j4 * 4) = o;
        }
    }
}

// =============================================================================
// softmax-one over rows of attn (in place): p = exp(x - max) / (1 + sum exp)
// one block (256 threads) per row of 2048
// =============================================================================
__global__ __launch_bounds__(256)
void softmax_one_k(float* __restrict__ attn)
{
    __shared__ float red[8];
    __shared__ float s_m, s_inv;

    float* p = attn + (long)blockIdx.x * TT;
    int tid = threadIdx.x;

    float4 v0 = *(float4*)(p + tid * 4);
    float4 v1 = *(float4*)(p + 1024 + tid * 4);

    float m = fmaxf(fmaxf(fmaxf(v0.x, v0.y), fmaxf(v0.z, v0.w)),
                    fmaxf(fmaxf(v1.x, v1.y), fmaxf(v1.z, v1.w)));
#pragma unroll
    for (int s = 16; s > 0; s >>= 1)
        m = fmaxf(m, __shfl_xor_sync(0xffffffffu, m, s));
    if ((tid & 31) == 0) red[tid >> 5] = m;
    __syncthreads();
    if (tid < 32) {
        float t = red[tid & 7];
#pragma unroll
        for (int s = 4; s > 0; s >>= 1)
            t = fmaxf(t, __shfl_xor_sync(0xffffffffu, t, s));
        if (tid == 0) s_m = t;
    }
    __syncthreads();
    m = s_m;

    v0.x = __expf(v0.x - m); v0.y = __expf(v0.y - m);
    v0.z = __expf(v0.z - m); v0.w = __expf(v0.w - m);
    v1.x = __expf(v1.x - m); v1.y = __expf(v1.y - m);
    v1.z = __expf(v1.z - m); v1.w = __expf(v1.w - m);

    float sum = v0.x + v0.y + v0.z + v0.w + v1.x + v1.y + v1.z + v1.w;
#pragma unroll
    for (int s = 16; s > 0; s >>= 1)
        sum += __shfl_xor_sync(0xffffffffu, sum, s);
    if ((tid & 31) == 0) red[tid >> 5] = sum;
    __syncthreads();
    if (tid < 32) {
        float t = red[tid & 7];
#pragma unroll
        for (int s = 4; s > 0; s >>= 1)
            t += __shfl_xor_sync(0xffffffffu, t, s);
        if (tid == 0) s_inv = 1.0f / (1.0f + t);   // softmax-one: +1 in denom
    }
    __syncthreads();
    float inv = s_inv;

    v0.x *= inv; v0.y *= inv; v0.z *= inv; v0.w *= inv;
    v1.x *= inv; v1.y *= inv; v1.z *= inv; v1.w *= inv;
    *(float4*)(p + tid * 4) = v0;
    *(float4*)(p + 1024 + tid * 4) = v1;
}

// =============================================================================
// AV GEMM (NN): per z=(b,h):  X[2048,64] = P[2048,2048] @ Vh[2048,64]
// P contiguous (ld=T), Vh/X strided into [B,T,D] layout (ld=D).
// 128x64 tile, BK=16, 256 threads, 8x4 per-thread tile.
// =============================================================================
__global__ __launch_bounds__(256)
void av_gemm(const float* __restrict__ P, const float* __restrict__ V,
             float* __restrict__ X)
{
    __shared__ float As[16][128];
    __shared__ float Bs[16][64];

    int z = blockIdx.z;
    int b = z >> 4, h = z & 15;
    const float* Pz = P + (long)z * TT * TT;
    const float* Vz = V + (long)b * TT * DD + h * DKK;
    float*       Xz = X + (long)b * TT * DD + h * DKK;

    int tid = threadIdx.x;
    int bm = blockIdx.y * 128;

    int tr = (tid >> 4) * 8;      // 0..120
    int tc = (tid & 15) * 4;      // 0..60

    float acc[8][4];
#pragma unroll
    for (int i = 0; i < 8; i++)
#pragma unroll
        for (int j = 0; j < 4; j++) acc[i][j] = 0.0f;

    for (int k0 = 0; k0 < TT; k0 += 16) {
#pragma unroll
        for (int jj = 0; jj < 2; jj++) {
            int e4 = tid + jj * 256;
            int row = e4 >> 2;
            int kk = (e4 & 3) * 4;
            float4 a = *(const float4*)(Pz + (long)(bm + row) * TT + k0 + kk);
            As[kk + 0][row] = a.x; As[kk + 1][row] = a.y;
            As[kk + 2][row] = a.z; As[kk + 3][row] = a.w;
        }
        {
            int brow = tid >> 4;
            int bc = (tid & 15) * 4;
            float4 bb = *(const float4*)(Vz + (long)(k0 + brow) * DD + bc);
            *(float4*)(&Bs[brow][bc]) = bb;
        }
        __syncthreads();
#pragma unroll
        for (int k = 0; k < 16; k++) {
            float af[8], bf[4];
            *(float4*)(af)     = *(const float4*)(&As[k][tr]);
            *(float4*)(af + 4) = *(const float4*)(&As[k][tr + 4]);
            *(float4*)(bf)     = *(const float4*)(&Bs[k][tc]);
#pragma unroll
            for (int i = 0; i < 8; i++)
#pragma unroll
                for (int j = 0; j < 4; j++)
                    acc[i][j] = fmaf(af[i], bf[j], acc[i][j]);
        }
        __syncthreads();
    }
#pragma unroll
    for (int i = 0; i < 8; i++)
        *(float4*)(Xz + (long)(bm + tr + i) * DD + tc) =
            make_float4(acc[i][0], acc[i][1], acc[i][2], acc[i][3]);
}

// =============================================================================
// residual + LayerNorm: y = LN(query + o) * gamma + beta ; one block per row
// =============================================================================
__global__ __launch_bounds__(256)
void resid_ln_k(const float* __restrict__ q, const float* __restrict__ o,
                const float* __restrict__ gamma, const float* __restrict__ beta,
                float* __restrict__ out)
{
    __shared__ float redA[8], redB[8];
    __shared__ float s_mu, s_rstd;

    long row = blockIdx.x;
    const float* qp = q + row * DD;
    const float* op = o + row * DD;
    float* yp = out + row * DD;
    int tid = threadIdx.x;

    float4 a = *(const float4*)(qp + tid * 4);
    float4 b = *(const float4*)(op + tid * 4);
    float4 y = make_float4(a.x + b.x, a.y + b.y, a.z + b.z, a.w + b.w);

    float s  = y.x + y.y + y.z + y.w;
    float s2 = y.x * y.x + y.y * y.y + y.z * y.z + y.w * y.w;
#pragma unroll
    for (int sh = 16; sh > 0; sh >>= 1) {
        s  += __shfl_xor_sync(0xffffffffu, s,  sh);
        s2 += __shfl_xor_sync(0xffffffffu, s2, sh);
    }
    if ((tid & 31) == 0) { redA[tid >> 5] = s; redB[tid >> 5] = s2; }
    __syncthreads();
    if (tid < 32) {
        float t  = redA[tid & 7];
        float t2 = redB[tid & 7];
#pragma unroll
        for (int sh = 4; sh > 0; sh >>= 1) {
            t  += __shfl_xor_sync(0xffffffffu, t,  sh);
            t2 += __shfl_xor_sync(0xffffffffu, t2, sh);
        }
        if (tid == 0) {
            float mu  = t / (float)DD;
            float var = t2 / (float)DD - mu * mu;
            s_mu = mu;
            s_rstd = rsqrtf(var + 1e-5f);
        }
    }
    __syncthreads();
    float mu = s_mu, rstd = s_rstd;

    float4 g = *(const float4*)(gamma + tid * 4);
    float4 be = *(const float4*)(beta + tid * 4);
    float4 r;
    r.x = (y.x - mu) * rstd * g.x + be.x;
    r.y = (y.y - mu) * rstd * g.y + be.y;
    r.z = (y.z - mu) * rstd * g.z + be.z;
    r.w = (y.w - mu) * rstd * g.w + be.w;
    *(float4*)(yp + tid * 4) = r;
}

// =============================================================================
extern "C" void kernel_launch(void* const* d_in, const int* in_sizes, int n_in,
                              void* d_out, int out_size)
{
    const float* query = (const float*)d_in[0];
    const float* key   = (const float*)d_in[1];
    const float* value = (const float*)d_in[2];
    const float* Wq = (const float*)d_in[3];
    const float* bq = (const float*)d_in[4];
    const float* Wk = (const float*)d_in[5];
    const float* bk = (const float*)d_in[6];
    const float* Wv = (const float*)d_in[7];
    const float* bv = (const float*)d_in[8];
    const float* Wo = (const float*)d_in[9];
    const float* bo = (const float*)d_in[10];
    const float* gamma = (const float*)d_in[11];
    const float* beta  = (const float*)d_in[12];

    float* out = (float*)d_out;

    float *q, *k, *v, *x, *o, *attn_scr;
    cudaGetSymbolAddress((void**)&q, g_q);
    cudaGetSymbolAddress((void**)&k, g_k);
    cudaGetSymbolAddress((void**)&v, g_v);
    cudaGetSymbolAddress((void**)&x, g_x);
    cudaGetSymbolAddress((void**)&o, g_o);
    cudaGetSymbolAddress((void**)&attn_scr, g_attn_scratch);

    const long y_elems    = (long)BB * TT * DD;               //   4,194,304
    const long attn_elems = (long)BB * HH * TT * TT;          // 134,217,728
    float* y_out = out;
    float* attn  = ((long)out_size >= y_elems + attn_elems) ? (out + y_elems)
                                                            : attn_scr;

    dim3 tpb(256);

    // QKV projections: [4096,1024] @ W^T + b
    dim3 gproj(DD / 128, BT / 128, 1);
    sgemm_nt<<<gproj, tpb>>>(query, DD, 0, 0, Wq, DD, 0, 0, q, DD, 0, bq, DD, 1.0f);
    sgemm_nt<<<gproj, tpb>>>(key,   DD, 0, 0, Wk, DD, 0, 0, k, DD, 0, bk, DD, 1.0f);
    sgemm_nt<<<gproj, tpb>>>(value, DD, 0, 0, Wv, DD, 0, 0, v, DD, 0, bv, DD, 1.0f);

    // scores: per (b,h): S = Qh @ Kh^T / 8  -> written straight into attn region
    dim3 gsc(TT / 128, TT / 128, BB * HH);
    sgemm_nt<<<gsc, tpb>>>(q, DD, (long)TT * DD, DKK,
                           k, DD, (long)TT * DD, DKK,
                           attn, TT, (long)TT * TT,
                           nullptr, DKK, 0.125f);

    // softmax-one in place
    softmax_one_k<<<BB * HH * TT, tpb>>>(attn);

    // x = attn @ V  (back into [B,T,D] layout)
    dim3 gav(1, TT / 128, BB * HH);
    av_gemm<<<gav, tpb>>>(attn, v, x);

    // output projection
    sgemm_nt<<<gproj, tpb>>>(x, DD, 0, 0, Wo, DD, 0, 0, o, DD, 0, bo, DD, 1.0f);

    // residual + LayerNorm -> y
    resid_ln_k<<<BT, tpb>>>(query, o, gamma, beta, y_out);
}

// round 3
// speedup vs baseline: 2.1873x; 2.1873x over previous
#include <cuda_runtime.h>
#include <cuda_bf16.h>
#include <cstdint>

#define BB 2
#define TT 2048
#define DD 1024
#define HH 16
#define DKK 64
#define BT 4096   // BB*TT

// ---------------- scratch (device globals; no runtime allocation) -------------
__device__ float g_q[(size_t)BT * DD];
__device__ float g_k[(size_t)BT * DD];
__device__ float g_v[(size_t)BT * DD];
__device__ float g_x[(size_t)BT * DD];
__device__ float g_o[(size_t)BT * DD];
// fallback attn scratch in case d_out only holds y (tuple handling safety)
__device__ float g_attn_scratch[(size_t)BB * HH * TT * TT];

// ----------------------------- helpers ---------------------------------------
__device__ __forceinline__ unsigned f2tf32(float x) {
    unsigned u;
    asm("cvt.rna.tf32.f32 %0, %1;" : "=r"(u) : "f"(x));
    return u;
}

__device__ __forceinline__ void mma_tf32(float c[4], const unsigned a[4], const unsigned b[2]) {
    asm volatile(
        "mma.sync.aligned.m16n8k8.row.col.f32.tf32.tf32.f32 "
        "{%0,%1,%2,%3}, {%4,%5,%6,%7}, {%8,%9}, {%0,%1,%2,%3};"
        : "+f"(c[0]), "+f"(c[1]), "+f"(c[2]), "+f"(c[3])
        : "r"(a[0]), "r"(a[1]), "r"(a[2]), "r"(a[3]), "r"(b[0]), "r"(b[1]));
}

// =============================================================================
// NT tf32 tensor-core GEMM: C[m,n] = alpha * sum_k A[m,k]*Bm[n,k] (+ bias[n])
// Batched over blockIdx.z like before. Tile 128x128, BK=32, 256 threads
// (8 warps in 2(m) x 4(n) grid; warp tile 64x32 = 4 m-frags x 4 n-frags).
// =============================================================================
#define SA 36   // smem row stride (floats) for [row][k] tiles, conflict-free frag loads

__global__ __launch_bounds__(256)
void mma_nt(const float* __restrict__ A, int lda, long sAb, long sAh,
            const float* __restrict__ Bm, int ldb, long sBb, long sBh,
            float* __restrict__ C, int ldc, long sCz,
            const float* __restrict__ bias, int K, float alpha)
{
    __shared__ unsigned As[128 * SA];   // [m][k]
    __shared__ unsigned Bs[128 * SA];   // [n][k]

    int z = blockIdx.z;
    A  += (long)(z >> 4) * sAb + (long)(z & 15) * sAh;
    Bm += (long)(z >> 4) * sBb + (long)(z & 15) * sBh;
    C  += (long)z * sCz;

    int tid = threadIdx.x;
    int lane = tid & 31, wid = tid >> 5;
    int g = lane >> 2, tg = lane & 3;
    int wm = (wid & 1) * 64;      // warp m offset
    int wn = (wid >> 1) * 32;     // warp n offset

    int bm = blockIdx.y * 128;
    int bn = blockIdx.x * 128;

    float acc[4][4][4];
#pragma unroll
    for (int i = 0; i < 4; i++)
#pragma unroll
        for (int j = 0; j < 4; j++)
#pragma unroll
            for (int r = 0; r < 4; r++) acc[i][j][r] = 0.0f;

    for (int k0 = 0; k0 < K; k0 += 32) {
        // load A,B tiles (128x32 each) as float4, convert to tf32 bits
#pragma unroll
        for (int i = 0; i < 4; i++) {
            int lin = tid + i * 256;
            int row = lin >> 3;
            int c4 = (lin & 7) * 4;
            float4 va = *(const float4*)(A + (long)(bm + row) * lda + k0 + c4);
            unsigned* pa = &As[row * SA + c4];
            pa[0] = f2tf32(va.x); pa[1] = f2tf32(va.y);
            pa[2] = f2tf32(va.z); pa[3] = f2tf32(va.w);
            float4 vb = *(const float4*)(Bm + (long)(bn + row) * ldb + k0 + c4);
            unsigned* pb = &Bs[row * SA + c4];
            pb[0] = f2tf32(vb.x); pb[1] = f2tf32(vb.y);
            pb[2] = f2tf32(vb.z); pb[3] = f2tf32(vb.w);
        }
        __syncthreads();

#pragma unroll
        for (int ks = 0; ks < 4; ks++) {
            int kb = ks * 8;
            unsigned a[4][4], b[4][2];
#pragma unroll
            for (int mf = 0; mf < 4; mf++) {
                int m = wm + mf * 16;
                a[mf][0] = As[(m + g) * SA + kb + tg];
                a[mf][1] = As[(m + g + 8) * SA + kb + tg];
                a[mf][2] = As[(m + g) * SA + kb + tg + 4];
                a[mf][3] = As[(m + g + 8) * SA + kb + tg + 4];
            }
#pragma unroll
            for (int nf = 0; nf < 4; nf++) {
                int n = wn + nf * 8;
                b[nf][0] = Bs[(n + g) * SA + kb + tg];
                b[nf][1] = Bs[(n + g) * SA + kb + tg + 4];
            }
#pragma unroll
            for (int mf = 0; mf < 4; mf++)
#pragma unroll
                for (int nf = 0; nf < 4; nf++)
                    mma_tf32(acc[mf][nf], a[mf], b[nf]);
        }
        __syncthreads();
    }

    // epilogue
#pragma unroll
    for (int mf = 0; mf < 4; mf++) {
#pragma unroll
        for (int nf = 0; nf < 4; nf++) {
            int m0 = bm + wm + mf * 16 + g;
            int n0 = bn + wn + nf * 8 + 2 * tg;
            float b0 = bias ? bias[n0] : 0.0f;
            float b1 = bias ? bias[n0 + 1] : 0.0f;
            float* c0 = C + (long)m0 * ldc + n0;
            float* c1 = C + (long)(m0 + 8) * ldc + n0;
            c0[0] = alpha * acc[mf][nf][0] + b0;
            c0[1] = alpha * acc[mf][nf][1] + b1;
            c1[0] = alpha * acc[mf][nf][2] + b0;
            c1[1] = alpha * acc[mf][nf][3] + b1;
        }
    }
}

// =============================================================================
// AV tf32 GEMM (NN): per z=(b,h): X[2048,64] = P[2048,2048] @ Vh[2048,64]
// Tile 128x64, BK=32, 256 threads (warp grid 4(m) x 2(n); warp tile 32x32).
// =============================================================================
#define SV 72   // Vs row stride (floats): conflict-free B-frag loads

__global__ __launch_bounds__(256)
void mma_av(const float* __restrict__ P, const float* __restrict__ V,
            float* __restrict__ X)
{
    __shared__ unsigned Ps[128 * SA];   // [m][k]
    __shared__ unsigned Vs[32 * SV];    // [k][n]

    int z = blockIdx.z;
    int b = z >> 4, h = z & 15;
    const float* Pz = P + (long)z * TT * TT;
    const float* Vz = V + (long)b * TT * DD + h * DKK;
    float*       Xz = X + (long)b * TT * DD + h * DKK;

    int tid = threadIdx.x;
    int lane = tid & 31, wid = tid >> 5;
    int g = lane >> 2, tg = lane & 3;
    int wm = (wid >> 1) * 32;     // 4 warps along M
    int wn = (wid & 1) * 32;      // 2 warps along N

    int bm = blockIdx.y * 128;

    float acc[2][4][4];
#pragma unroll
    for (int i = 0; i < 2; i++)
#pragma unroll
        for (int j = 0; j < 4; j++)
#pragma unroll
            for (int r = 0; r < 4; r++) acc[i][j][r] = 0.0f;

    for (int k0 = 0; k0 < TT; k0 += 32) {
        // load P tile 128x32
#pragma unroll
        for (int i = 0; i < 4; i++) {
            int lin = tid + i * 256;
            int row = lin >> 3;
            int c4 = (lin & 7) * 4;
            float4 va = *(const float4*)(Pz + (long)(bm + row) * TT + k0 + c4);
            unsigned* pa = &Ps[row * SA + c4];
            pa[0] = f2tf32(va.x); pa[1] = f2tf32(va.y);
            pa[2] = f2tf32(va.z); pa[3] = f2tf32(va.w);
        }
        // load V tile 32(k) x 64(n)
#pragma unroll
        for (int i = 0; i < 2; i++) {
            int lin = tid + i * 256;
            int row = lin >> 4;          // k row 0..31
            int c4 = (lin & 15) * 4;     // n col
            float4 vv = *(const float4*)(Vz + (long)(k0 + row) * DD + c4);
            unsigned* pv = &Vs[row * SV + c4];
            pv[0] = f2tf32(vv.x); pv[1] = f2tf32(vv.y);
            pv[2] = f2tf32(vv.z); pv[3] = f2tf32(vv.w);
        }
        __syncthreads();

#pragma unroll
        for (int ks = 0; ks < 4; ks++) {
            int kb = ks * 8;
            unsigned a[2][4], bfr[4][2];
#pragma unroll
            for (int mf = 0; mf < 2; mf++) {
                int m = wm + mf * 16;
                a[mf][0] = Ps[(m + g) * SA + kb + tg];
                a[mf][1] = Ps[(m + g + 8) * SA + kb + tg];
                a[mf][2] = Ps[(m + g) * SA + kb + tg + 4];
                a[mf][3] = Ps[(m + g + 8) * SA + kb + tg + 4];
            }
#pragma unroll
            for (int nf = 0; nf < 4; nf++) {
                int n = wn + nf * 8;
                bfr[nf][0] = Vs[(kb + tg) * SV + n + g];
                bfr[nf][1] = Vs[(kb + tg + 4) * SV + n + g];
            }
#pragma unroll
            for (int mf = 0; mf < 2; mf++)
#pragma unroll
                for (int nf = 0; nf < 4; nf++)
                    mma_tf32(acc[mf][nf], a[mf], bfr[nf]);
        }
        __syncthreads();
    }

#pragma unroll
    for (int mf = 0; mf < 2; mf++) {
#pragma unroll
        for (int nf = 0; nf < 4; nf++) {
            int m0 = bm + wm + mf * 16 + g;
            int n0 = wn + nf * 8 + 2 * tg;
            float* c0 = Xz + (long)m0 * DD + n0;
            float* c1 = Xz + (long)(m0 + 8) * DD + n0;
            c0[0] = acc[mf][nf][0];
            c0[1] = acc[mf][nf][1];
            c1[0] = acc[mf][nf][2];
            c1[1] = acc[mf][nf][3];
        }
    }
}

// =============================================================================
// softmax-one over rows of attn (in place): p = exp(x - max) / (1 + sum exp)
// one block (256 threads) per row of 2048
// =============================================================================
__global__ __launch_bounds__(256)
void softmax_one_k(float* __restrict__ attn)
{
    __shared__ float red[8];
    __shared__ float s_m, s_inv;

    float* p = attn + (long)blockIdx.x * TT;
    int tid = threadIdx.x;

    float4 v0 = *(float4*)(p + tid * 4);
    float4 v1 = *(float4*)(p + 1024 + tid * 4);

    float m = fmaxf(fmaxf(fmaxf(v0.x, v0.y), fmaxf(v0.z, v0.w)),
                    fmaxf(fmaxf(v1.x, v1.y), fmaxf(v1.z, v1.w)));
#pragma unroll
    for (int s = 16; s > 0; s >>= 1)
        m = fmaxf(m, __shfl_xor_sync(0xffffffffu, m, s));
    if ((tid & 31) == 0) red[tid >> 5] = m;
    __syncthreads();
    if (tid < 32) {
        float t = red[tid & 7];
#pragma unroll
        for (int s = 4; s > 0; s >>= 1)
            t = fmaxf(t, __shfl_xor_sync(0xffffffffu, t, s));
        if (tid == 0) s_m = t;
    }
    __syncthreads();
    m = s_m;

    v0.x = __expf(v0.x - m); v0.y = __expf(v0.y - m);
    v0.z = __expf(v0.z - m); v0.w = __expf(v0.w - m);
    v1.x = __expf(v1.x - m); v1.y = __expf(v1.y - m);
    v1.z = __expf(v1.z - m); v1.w = __expf(v1.w - m);

    float sum = v0.x + v0.y + v0.z + v0.w + v1.x + v1.y + v1.z + v1.w;
#pragma unroll
    for (int s = 16; s > 0; s >>= 1)
        sum += __shfl_xor_sync(0xffffffffu, sum, s);
    if ((tid & 31) == 0) red[tid >> 5] = sum;
    __syncthreads();
    if (tid < 32) {
        float t = red[tid & 7];
#pragma unroll
        for (int s = 4; s > 0; s >>= 1)
            t += __shfl_xor_sync(0xffffffffu, t, s);
        if (tid == 0) s_inv = 1.0f / (1.0f + t);   // softmax-one: +1 in denom
    }
    __syncthreads();
    float inv = s_inv;

    v0.x *= inv; v0.y *= inv; v0.z *= inv; v0.w *= inv;
    v1.x *= inv; v1.y *= inv; v1.z *= inv; v1.w *= inv;
    *(float4*)(p + tid * 4) = v0;
    *(float4*)(p + 1024 + tid * 4) = v1;
}

// =============================================================================
// residual + LayerNorm: y = LN(query + o) * gamma + beta ; one block per row
// =============================================================================
__global__ __launch_bounds__(256)
void resid_ln_k(const float* __restrict__ q, const float* __restrict__ o,
                const float* __restrict__ gamma, const float* __restrict__ beta,
                float* __restrict__ out)
{
    __shared__ float redA[8], redB[8];
    __shared__ float s_mu, s_rstd;

    long row = blockIdx.x;
    const float* qp = q + row * DD;
    const float* op = o + row * DD;
    float* yp = out + row * DD;
    int tid = threadIdx.x;

    float4 a = *(const float4*)(qp + tid * 4);
    float4 b = *(const float4*)(op + tid * 4);
    float4 y = make_float4(a.x + b.x, a.y + b.y, a.z + b.z, a.w + b.w);

    float s  = y.x + y.y + y.z + y.w;
    float s2 = y.x * y.x + y.y * y.y + y.z * y.z + y.w * y.w;
#pragma unroll
    for (int sh = 16; sh > 0; sh >>= 1) {
        s  += __shfl_xor_sync(0xffffffffu, s,  sh);
        s2 += __shfl_xor_sync(0xffffffffu, s2, sh);
    }
    if ((tid & 31) == 0) { redA[tid >> 5] = s; redB[tid >> 5] = s2; }
    __syncthreads();
    if (tid < 32) {
        float t  = redA[tid & 7];
        float t2 = redB[tid & 7];
#pragma unroll
        for (int sh = 4; sh > 0; sh >>= 1) {
            t  += __shfl_xor_sync(0xffffffffu, t,  sh);
            t2 += __shfl_xor_sync(0xffffffffu, t2, sh);
        }
        if (tid == 0) {
            float mu  = t / (float)DD;
            float var = t2 / (float)DD - mu * mu;
            s_mu = mu;
            s_rstd = rsqrtf(var + 1e-5f);
        }
    }
    __syncthreads();
    float mu = s_mu, rstd = s_rstd;

    float4 g = *(const float4*)(gamma + tid * 4);
    float4 be = *(const float4*)(beta + tid * 4);
    float4 r;
    r.x = (y.x - mu) * rstd * g.x + be.x;
    r.y = (y.y - mu) * rstd * g.y + be.y;
    r.z = (y.z - mu) * rstd * g.z + be.z;
    r.w = (y.w - mu) * rstd * g.w + be.w;
    *(float4*)(yp + tid * 4) = r;
}

// =============================================================================
extern "C" void kernel_launch(void* const* d_in, const int* in_sizes, int n_in,
                              void* d_out, int out_size)
{
    const float* query = (const float*)d_in[0];
    const float* key   = (const float*)d_in[1];
    const float* value = (const float*)d_in[2];
    const float* Wq = (const float*)d_in[3];
    const float* bq = (const float*)d_in[4];
    const float* Wk = (const float*)d_in[5];
    const float* bk = (const float*)d_in[6];
    const float* Wv = (const float*)d_in[7];
    const float* bv = (const float*)d_in[8];
    const float* Wo = (const float*)d_in[9];
    const float* bo = (const float*)d_in[10];
    const float* gamma = (const float*)d_in[11];
    const float* beta  = (const float*)d_in[12];

    float* out = (float*)d_out;

    float *q, *k, *v, *x, *o, *attn_scr;
    cudaGetSymbolAddress((void**)&q, g_q);
    cudaGetSymbolAddress((void**)&k, g_k);
    cudaGetSymbolAddress((void**)&v, g_v);
    cudaGetSymbolAddress((void**)&x, g_x);
    cudaGetSymbolAddress((void**)&o, g_o);
    cudaGetSymbolAddress((void**)&attn_scr, g_attn_scratch);

    const long y_elems    = (long)BB * TT * DD;               //   4,194,304
    const long attn_elems = (long)BB * HH * TT * TT;          // 134,217,728
    float* y_out = out;
    float* attn  = ((long)out_size >= y_elems + attn_elems) ? (out + y_elems)
                                                            : attn_scr;

    dim3 tpb(256);

    // QKV projections: [4096,1024] @ W^T + b  (tensor cores, tf32)
    dim3 gproj(DD / 128, BT / 128, 1);
    mma_nt<<<gproj, tpb>>>(query, DD, 0, 0, Wq, DD, 0, 0, q, DD, 0, bq, DD, 1.0f);
    mma_nt<<<gproj, tpb>>>(key,   DD, 0, 0, Wk, DD, 0, 0, k, DD, 0, bk, DD, 1.0f);
    mma_nt<<<gproj, tpb>>>(value, DD, 0, 0, Wv, DD, 0, 0, v, DD, 0, bv, DD, 1.0f);

    // scores: per (b,h): S = Qh @ Kh^T / 8  -> written straight into attn region
    dim3 gsc(TT / 128, TT / 128, BB * HH);
    mma_nt<<<gsc, tpb>>>(q, DD, (long)TT * DD, DKK,
                         k, DD, (long)TT * DD, DKK,
                         attn, TT, (long)TT * TT,
                         nullptr, DKK, 0.125f);

    // softmax-one in place
    softmax_one_k<<<BB * HH * TT, tpb>>>(attn);

    // x = attn @ V  (back into [B,T,D] layout)
    dim3 gav(1, TT / 128, BB * HH);
    mma_av<<<gav, tpb>>>(attn, v, x);

    // output projection
    mma_nt<<<gproj, tpb>>>(x, DD, 0, 0, Wo, DD, 0, 0, o, DD, 0, bo, DD, 1.0f);

    // residual + LayerNorm -> y
    resid_ln_k<<<BT, tpb>>>(query, o, gamma, beta, y_out);
}

// round 4
// speedup vs baseline: 2.2296x; 1.0193x over previous
#include <cuda_runtime.h>
#include <cuda_bf16.h>
#include <cstdint>

#define BB 2
#define TT 2048
#define DD 1024
#define HH 16
#define DKK 64
#define BT 4096   // BB*TT

// ---------------- scratch (device globals; no runtime allocation) -------------
__device__ float g_q[(size_t)BT * DD];
__device__ float g_k[(size_t)BT * DD];
__device__ float g_v[(size_t)BT * DD];
__device__ float g_x[(size_t)BT * DD];
__device__ float g_o[(size_t)BT * DD];
// fallback attn scratch in case d_out only holds y (tuple handling safety)
__device__ float g_attn_scratch[(size_t)BB * HH * TT * TT];

// ----------------------------- helpers ---------------------------------------
__device__ __forceinline__ unsigned f2tf32(float x) {
    unsigned u;
    asm("cvt.rna.tf32.f32 %0, %1;" : "=r"(u) : "f"(x));
    return u;
}

__device__ __forceinline__ void mma_tf32(float c[4], const unsigned a[4], const unsigned b[2]) {
    asm volatile(
        "mma.sync.aligned.m16n8k8.row.col.f32.tf32.tf32.f32 "
        "{%0,%1,%2,%3}, {%4,%5,%6,%7}, {%8,%9}, {%0,%1,%2,%3};"
        : "+f"(c[0]), "+f"(c[1]), "+f"(c[2]), "+f"(c[3])
        : "r"(a[0]), "r"(a[1]), "r"(a[2]), "r"(a[3]), "r"(b[0]), "r"(b[1]));
}

// =============================================================================
// NT tf32 tensor-core GEMM with register-prefetch pipeline.
// C[m,n] = alpha * sum_k A[m,k]*Bm[n,k] (+ bias[n]); batched over blockIdx.z.
// Tile 128x128, BK=16, 256 threads (8 warps in 2(m) x 4(n); warp tile 64x32).
// Next k-tile's LDGs are issued right after syncthreads and consumed next
// iteration, hiding gmem latency behind the mma+LDS section.
// =============================================================================
#define SK16 20   // smem row stride (floats) for BK=16 tiles; conflict-free

__global__ __launch_bounds__(256, 2)
void mma_nt(const float* __restrict__ A, int lda, long sAb, long sAh,
            const float* __restrict__ Bm, int ldb, long sBb, long sBh,
            float* __restrict__ C, int ldc, long sCz,
            const float* __restrict__ bias, int K, float alpha)
{
    __shared__ unsigned As[128 * SK16];   // [m][k]
    __shared__ unsigned Bs[128 * SK16];   // [n][k]

    int z = blockIdx.z;
    A  += (long)(z >> 4) * sAb + (long)(z & 15) * sAh;
    Bm += (long)(z >> 4) * sBb + (long)(z & 15) * sBh;
    C  += (long)z * sCz;

    int tid = threadIdx.x;
    int lane = tid & 31, wid = tid >> 5;
    int g = lane >> 2, tg = lane & 3;
    int wm = (wid & 1) * 64;      // warp m offset
    int wn = (wid >> 1) * 32;     // warp n offset

    int bm = blockIdx.y * 128;
    int bn = blockIdx.x * 128;

    // loader mapping: 4 threads per row (16 floats), 64 rows per slab
    int lrow = tid >> 2;          // 0..63
    int lc4  = (tid & 3) * 4;

    const float* Ar0 = A  + (long)(bm + lrow) * lda + lc4;
    const float* Ar1 = A  + (long)(bm + lrow + 64) * lda + lc4;
    const float* Br0 = Bm + (long)(bn + lrow) * ldb + lc4;
    const float* Br1 = Bm + (long)(bn + lrow + 64) * ldb + lc4;

    float acc[4][4][4];
#pragma unroll
    for (int i = 0; i < 4; i++)
#pragma unroll
        for (int j = 0; j < 4; j++)
#pragma unroll
            for (int r = 0; r < 4; r++) acc[i][j][r] = 0.0f;

    // prefetch k-tile 0
    float4 pa0 = *(const float4*)(Ar0);
    float4 pa1 = *(const float4*)(Ar1);
    float4 pb0 = *(const float4*)(Br0);
    float4 pb1 = *(const float4*)(Br1);

    for (int k0 = 0; k0 < K; k0 += 16) {
        // commit prefetched tile to smem (with RNA tf32 conversion)
        unsigned* da0 = &As[lrow * SK16 + lc4];
        da0[0] = f2tf32(pa0.x); da0[1] = f2tf32(pa0.y);
        da0[2] = f2tf32(pa0.z); da0[3] = f2tf32(pa0.w);
        unsigned* da1 = &As[(lrow + 64) * SK16 + lc4];
        da1[0] = f2tf32(pa1.x); da1[1] = f2tf32(pa1.y);
        da1[2] = f2tf32(pa1.z); da1[3] = f2tf32(pa1.w);
        unsigned* db0 = &Bs[lrow * SK16 + lc4];
        db0[0] = f2tf32(pb0.x); db0[1] = f2tf32(pb0.y);
        db0[2] = f2tf32(pb0.z); db0[3] = f2tf32(pb0.w);
        unsigned* db1 = &Bs[(lrow + 64) * SK16 + lc4];
        db1[0] = f2tf32(pb1.x); db1[1] = f2tf32(pb1.y);
        db1[2] = f2tf32(pb1.z); db1[3] = f2tf32(pb1.w);
        __syncthreads();

        // issue next tile's loads early; consumed next iteration
        if (k0 + 16 < K) {
            pa0 = *(const float4*)(Ar0 + k0 + 16);
            pa1 = *(const float4*)(Ar1 + k0 + 16);
            pb0 = *(const float4*)(Br0 + k0 + 16);
            pb1 = *(const float4*)(Br1 + k0 + 16);
        }

#pragma unroll
        for (int ks = 0; ks < 2; ks++) {
            int kb = ks * 8;
            unsigned a[4][4], b[4][2];
#pragma unroll
            for (int mf = 0; mf < 4; mf++) {
                int m = wm + mf * 16;
                a[mf][0] = As[(m + g) * SK16 + kb + tg];
                a[mf][1] = As[(m + g + 8) * SK16 + kb + tg];
                a[mf][2] = As[(m + g) * SK16 + kb + tg + 4];
                a[mf][3] = As[(m + g + 8) * SK16 + kb + tg + 4];
            }
#pragma unroll
            for (int nf = 0; nf < 4; nf++) {
                int n = wn + nf * 8;
                b[nf][0] = Bs[(n + g) * SK16 + kb + tg];
                b[nf][1] = Bs[(n + g) * SK16 + kb + tg + 4];
            }
#pragma unroll
            for (int mf = 0; mf < 4; mf++)
#pragma unroll
                for (int nf = 0; nf < 4; nf++)
                    mma_tf32(acc[mf][nf], a[mf], b[nf]);
        }
        __syncthreads();
    }

    // epilogue
#pragma unroll
    for (int mf = 0; mf < 4; mf++) {
#pragma unroll
        for (int nf = 0; nf < 4; nf++) {
            int m0 = bm + wm + mf * 16 + g;
            int n0 = bn + wn + nf * 8 + 2 * tg;
            float b0 = bias ? bias[n0] : 0.0f;
            float b1 = bias ? bias[n0 + 1] : 0.0f;
            float* c0 = C + (long)m0 * ldc + n0;
            float* c1 = C + (long)(m0 + 8) * ldc + n0;
            c0[0] = alpha * acc[mf][nf][0] + b0;
            c0[1] = alpha * acc[mf][nf][1] + b1;
            c1[0] = alpha * acc[mf][nf][2] + b0;
            c1[1] = alpha * acc[mf][nf][3] + b1;
        }
    }
}

// =============================================================================
// AV tf32 GEMM (NN) with register-prefetch pipeline: per z=(b,h):
// X[2048,64] = P[2048,2048] @ Vh[2048,64]
// Tile 128x64, BK=32, 256 threads (warp grid 4(m) x 2(n); warp tile 32x32).
// =============================================================================
#define SK32 36   // P smem row stride (floats) for BK=32
#define SV 72     // V smem row stride

__global__ __launch_bounds__(256, 2)
void mma_av(const float* __restrict__ P, const float* __restrict__ V,
            float* __restrict__ X)
{
    __shared__ unsigned Ps[128 * SK32];   // [m][k]
    __shared__ unsigned Vs[32 * SV];      // [k][n]

    int z = blockIdx.z;
    int b = z >> 4, h = z & 15;
    const float* Pz = P + (long)z * TT * TT;
    const float* Vz = V + (long)b * TT * DD + h * DKK;
    float*       Xz = X + (long)b * TT * DD + h * DKK;

    int tid = threadIdx.x;
    int lane = tid & 31, wid = tid >> 5;
    int g = lane >> 2, tg = lane & 3;
    int wm = (wid >> 1) * 32;     // 4 warps along M
    int wn = (wid & 1) * 32;      // 2 warps along N

    int bm = blockIdx.y * 128;

    // P loader: 8 threads/row (32 floats), 32 rows per slab, 4 slabs
    int prow = tid >> 3;          // 0..31
    int pc4  = (tid & 7) * 4;
    // V loader: 16 threads/row (64 floats), 16 rows per slab, 2 slabs
    int vrow = tid >> 4;          // 0..15
    int vc4  = (tid & 15) * 4;

    const float* Pr[4];
#pragma unroll
    for (int i = 0; i < 4; i++)
        Pr[i] = Pz + (long)(bm + prow + i * 32) * TT + pc4;
    const float* Vr0 = Vz + (long)vrow * DD + vc4;
    const float* Vr1 = Vz + (long)(vrow + 16) * DD + vc4;

    float acc[2][4][4];
#pragma unroll
    for (int i = 0; i < 2; i++)
#pragma unroll
        for (int j = 0; j < 4; j++)
#pragma unroll
            for (int r = 0; r < 4; r++) acc[i][j][r] = 0.0f;

    float4 pp[4], pv0, pv1;
#pragma unroll
    for (int i = 0; i < 4; i++) pp[i] = *(const float4*)(Pr[i]);
    pv0 = *(const float4*)(Vr0);
    pv1 = *(const float4*)(Vr1);

    for (int k0 = 0; k0 < TT; k0 += 32) {
#pragma unroll
        for (int i = 0; i < 4; i++) {
            unsigned* dp = &Ps[(prow + i * 32) * SK32 + pc4];
            dp[0] = f2tf32(pp[i].x); dp[1] = f2tf32(pp[i].y);
            dp[2] = f2tf32(pp[i].z); dp[3] = f2tf32(pp[i].w);
        }
        {
            unsigned* dv = &Vs[vrow * SV + vc4];
            dv[0] = f2tf32(pv0.x); dv[1] = f2tf32(pv0.y);
            dv[2] = f2tf32(pv0.z); dv[3] = f2tf32(pv0.w);
            unsigned* dv1 = &Vs[(vrow + 16) * SV + vc4];
            dv1[0] = f2tf32(pv1.x); dv1[1] = f2tf32(pv1.y);
            dv1[2] = f2tf32(pv1.z); dv1[3] = f2tf32(pv1.w);
        }
        __syncthreads();

        if (k0 + 32 < TT) {
#pragma unroll
            for (int i = 0; i < 4; i++) pp[i] = *(const float4*)(Pr[i] + k0 + 32);
            pv0 = *(const float4*)(Vr0 + (long)(k0 + 32) * DD);
            pv1 = *(const float4*)(Vr1 + (long)(k0 + 32) * DD);
        }

#pragma unroll
        for (int ks = 0; ks < 4; ks++) {
            int kb = ks * 8;
            unsigned a[2][4], bfr[4][2];
#pragma unroll
            for (int mf = 0; mf < 2; mf++) {
                int m = wm + mf * 16;
                a[mf][0] = Ps[(m + g) * SK32 + kb + tg];
                a[mf][1] = Ps[(m + g + 8) * SK32 + kb + tg];
                a[mf][2] = Ps[(m + g) * SK32 + kb + tg + 4];
                a[mf][3] = Ps[(m + g + 8) * SK32 + kb + tg + 4];
            }
#pragma unroll
            for (int nf = 0; nf < 4; nf++) {
                int n = wn + nf * 8;
                bfr[nf][0] = Vs[(kb + tg) * SV + n + g];
                bfr[nf][1] = Vs[(kb + tg + 4) * SV + n + g];
            }
#pragma unroll
            for (int mf = 0; mf < 2; mf++)
#pragma unroll
                for (int nf = 0; nf < 4; nf++)
                    mma_tf32(acc[mf][nf], a[mf], bfr[nf]);
        }
        __syncthreads();
    }

#pragma unroll
    for (int mf = 0; mf < 2; mf++) {
#pragma unroll
        for (int nf = 0; nf < 4; nf++) {
            int m0 = bm + wm + mf * 16 + g;
            int n0 = wn + nf * 8 + 2 * tg;
            float* c0 = Xz + (long)m0 * DD + n0;
            float* c1 = Xz + (long)(m0 + 8) * DD + n0;
            c0[0] = acc[mf][nf][0];
            c0[1] = acc[mf][nf][1];
            c1[0] = acc[mf][nf][2];
            c1[1] = acc[mf][nf][3];
        }
    }
}

// =============================================================================
// softmax-one over rows of attn (in place): p = exp(x - max) / (1 + sum exp)
// one block (256 threads) per row of 2048
// =============================================================================
__global__ __launch_bounds__(256)
void softmax_one_k(float* __restrict__ attn)
{
    __shared__ float red[8];
    __shared__ float s_m, s_inv;

    float* p = attn + (long)blockIdx.x * TT;
    int tid = threadIdx.x;

    float4 v0 = *(float4*)(p + tid * 4);
    float4 v1 = *(float4*)(p + 1024 + tid * 4);

    float m = fmaxf(fmaxf(fmaxf(v0.x, v0.y), fmaxf(v0.z, v0.w)),
                    fmaxf(fmaxf(v1.x, v1.y), fmaxf(v1.z, v1.w)));
#pragma unroll
    for (int s = 16; s > 0; s >>= 1)
        m = fmaxf(m, __shfl_xor_sync(0xffffffffu, m, s));
    if ((tid & 31) == 0) red[tid >> 5] = m;
    __syncthreads();
    if (tid < 32) {
        float t = red[tid & 7];
#pragma unroll
        for (int s = 4; s > 0; s >>= 1)
            t = fmaxf(t, __shfl_xor_sync(0xffffffffu, t, s));
        if (tid == 0) s_m = t;
    }
    __syncthreads();
    m = s_m;

    v0.x = __expf(v0.x - m); v0.y = __expf(v0.y - m);
    v0.z = __expf(v0.z - m); v0.w = __expf(v0.w - m);
    v1.x = __expf(v1.x - m); v1.y = __expf(v1.y - m);
    v1.z = __expf(v1.z - m); v1.w = __expf(v1.w - m);

    float sum = v0.x + v0.y + v0.z + v0.w + v1.x + v1.y + v1.z + v1.w;
#pragma unroll
    for (int s = 16; s > 0; s >>= 1)
        sum += __shfl_xor_sync(0xffffffffu, sum, s);
    if ((tid & 31) == 0) red[tid >> 5] = sum;
    __syncthreads();
    if (tid < 32) {
        float t = red[tid & 7];
#pragma unroll
        for (int s = 4; s > 0; s >>= 1)
            t += __shfl_xor_sync(0xffffffffu, t, s);
        if (tid == 0) s_inv = 1.0f / (1.0f + t);   // softmax-one: +1 in denom
    }
    __syncthreads();
    float inv = s_inv;

    v0.x *= inv; v0.y *= inv; v0.z *= inv; v0.w *= inv;
    v1.x *= inv; v1.y *= inv; v1.z *= inv; v1.w *= inv;
    *(float4*)(p + tid * 4) = v0;
    *(float4*)(p + 1024 + tid * 4) = v1;
}

// =============================================================================
// residual + LayerNorm: y = LN(query + o) * gamma + beta ; one block per row
// =============================================================================
__global__ __launch_bounds__(256)
void resid_ln_k(const float* __restrict__ q, const float* __restrict__ o,
                const float* __restrict__ gamma, const float* __restrict__ beta,
                float* __restrict__ out)
{
    __shared__ float redA[8], redB[8];
    __shared__ float s_mu, s_rstd;

    long row = blockIdx.x;
    const float* qp = q + row * DD;
    const float* op = o + row * DD;
    float* yp = out + row * DD;
    int tid = threadIdx.x;

    float4 a = *(const float4*)(qp + tid * 4);
    float4 b = *(const float4*)(op + tid * 4);
    float4 y = make_float4(a.x + b.x, a.y + b.y, a.z + b.z, a.w + b.w);

    float s  = y.x + y.y + y.z + y.w;
    float s2 = y.x * y.x + y.y * y.y + y.z * y.z + y.w * y.w;
#pragma unroll
    for (int sh = 16; sh > 0; sh >>= 1) {
        s  += __shfl_xor_sync(0xffffffffu, s,  sh);
        s2 += __shfl_xor_sync(0xffffffffu, s2, sh);
    }
    if ((tid & 31) == 0) { redA[tid >> 5] = s; redB[tid >> 5] = s2; }
    __syncthreads();
    if (tid < 32) {
        float t  = redA[tid & 7];
        float t2 = redB[tid & 7];
#pragma unroll
        for (int sh = 4; sh > 0; sh >>= 1) {
            t  += __shfl_xor_sync(0xffffffffu, t,  sh);
            t2 += __shfl_xor_sync(0xffffffffu, t2, sh);
        }
        if (tid == 0) {
            float mu  = t / (float)DD;
            float var = t2 / (float)DD - mu * mu;
            s_mu = mu;
            s_rstd = rsqrtf(var + 1e-5f);
        }
    }
    __syncthreads();
    float mu = s_mu, rstd = s_rstd;

    float4 g = *(const float4*)(gamma + tid * 4);
    float4 be = *(const float4*)(beta + tid * 4);
    float4 r;
    r.x = (y.x - mu) * rstd * g.x + be.x;
    r.y = (y.y - mu) * rstd * g.y + be.y;
    r.z = (y.z - mu) * rstd * g.z + be.z;
    r.w = (y.w - mu) * rstd * g.w + be.w;
    *(float4*)(yp + tid * 4) = r;
}

// =============================================================================
extern "C" void kernel_launch(void* const* d_in, const int* in_sizes, int n_in,
                              void* d_out, int out_size)
{
    const float* query = (const float*)d_in[0];
    const float* key   = (const float*)d_in[1];
    const float* value = (const float*)d_in[2];
    const float* Wq = (const float*)d_in[3];
    const float* bq = (const float*)d_in[4];
    const float* Wk = (const float*)d_in[5];
    const float* bk = (const float*)d_in[6];
    const float* Wv = (const float*)d_in[7];
    const float* bv = (const float*)d_in[8];
    const float* Wo = (const float*)d_in[9];
    const float* bo = (const float*)d_in[10];
    const float* gamma = (const float*)d_in[11];
    const float* beta  = (const float*)d_in[12];

    float* out = (float*)d_out;

    float *q, *k, *v, *x, *o, *attn_scr;
    cudaGetSymbolAddress((void**)&q, g_q);
    cudaGetSymbolAddress((void**)&k, g_k);
    cudaGetSymbolAddress((void**)&v, g_v);
    cudaGetSymbolAddress((void**)&x, g_x);
    cudaGetSymbolAddress((void**)&o, g_o);
    cudaGetSymbolAddress((void**)&attn_scr, g_attn_scratch);

    const long y_elems    = (long)BB * TT * DD;               //   4,194,304
    const long attn_elems = (long)BB * HH * TT * TT;          // 134,217,728
    float* y_out = out;
    float* attn  = ((long)out_size >= y_elems + attn_elems) ? (out + y_elems)
                                                            : attn_scr;

    dim3 tpb(256);

    // QKV projections: [4096,1024] @ W^T + b  (tensor cores, tf32)
    dim3 gproj(DD / 128, BT / 128, 1);
    mma_nt<<<gproj, tpb>>>(query, DD, 0, 0, Wq, DD, 0, 0, q, DD, 0, bq, DD, 1.0f);
    mma_nt<<<gproj, tpb>>>(key,   DD, 0, 0, Wk, DD, 0, 0, k, DD, 0, bk, DD, 1.0f);
    mma_nt<<<gproj, tpb>>>(value, DD, 0, 0, Wv, DD, 0, 0, v, DD, 0, bv, DD, 1.0f);

    // scores: per (b,h): S = Qh @ Kh^T / 8  -> written straight into attn region
    dim3 gsc(TT / 128, TT / 128, BB * HH);
    mma_nt<<<gsc, tpb>>>(q, DD, (long)TT * DD, DKK,
                         k, DD, (long)TT * DD, DKK,
                         attn, TT, (long)TT * TT,
                         nullptr, DKK, 0.125f);

    // softmax-one in place
    softmax_one_k<<<BB * HH * TT, tpb>>>(attn);

    // x = attn @ V  (back into [B,T,D] layout)
    dim3 gav(1, TT / 128, BB * HH);
    mma_av<<<gav, tpb>>>(attn, v, x);

    // output projection
    mma_nt<<<gproj, tpb>>>(x, DD, 0, 0, Wo, DD, 0, 0, o, DD, 0, bo, DD, 1.0f);

    // residual + LayerNorm -> y
    resid_ln_k<<<BT, tpb>>>(query, o, gamma, beta, y_out);
}

// round 5
// speedup vs baseline: 2.4646x; 1.1054x over previous
#include <cuda_runtime.h>
#include <cstdint>

#define BB 2
#define TT 2048
#define DD 1024
#define HH 16
#define DKK 64
#define BT 4096   // BB*TT

// ---------------- scratch (device globals; no runtime allocation) -------------
__device__ float g_q[(size_t)BT * DD];
__device__ float g_k[(size_t)BT * DD];
__device__ float g_v[(size_t)BT * DD];
__device__ float g_x[(size_t)BT * DD];
__device__ float g_o[(size_t)BT * DD];
// fallback attn scratch in case d_out only holds y (tuple handling safety)
__device__ float g_attn_scratch[(size_t)BB * HH * TT * TT];

// ----------------------------- helpers ---------------------------------------
__device__ __forceinline__ unsigned f2tf32(float x) {
    unsigned u;
    asm("cvt.rna.tf32.f32 %0, %1;" : "=r"(u) : "f"(x));
    return u;
}

__device__ __forceinline__ void mma_tf32(float c[4], const unsigned a[4], const unsigned b[2]) {
    asm volatile(
        "mma.sync.aligned.m16n8k8.row.col.f32.tf32.tf32.f32 "
        "{%0,%1,%2,%3}, {%4,%5,%6,%7}, {%8,%9}, {%0,%1,%2,%3};"
        : "+f"(c[0]), "+f"(c[1]), "+f"(c[2]), "+f"(c[3])
        : "r"(a[0]), "r"(a[1]), "r"(a[2]), "r"(a[3]), "r"(b[0]), "r"(b[1]));
}

// =============================================================================
// NT tf32 tensor-core GEMM with register-prefetch pipeline (projections).
// C[m,n] = alpha * sum_k A[m,k]*Bm[n,k] (+ bias[n]).
// Tile 128x128, BK=16, 256 threads (8 warps in 2(m) x 4(n); warp tile 64x32).
// =============================================================================
#define SK16 20

__global__ __launch_bounds__(256, 2)
void mma_nt(const float* __restrict__ A, int lda,
            const float* __restrict__ Bm, int ldb,
            float* __restrict__ C, int ldc,
            const float* __restrict__ bias, int K, float alpha)
{
    __shared__ unsigned As[128 * SK16];   // [m][k]
    __shared__ unsigned Bs[128 * SK16];   // [n][k]

    int tid = threadIdx.x;
    int lane = tid & 31, wid = tid >> 5;
    int g = lane >> 2, tg = lane & 3;
    int wm = (wid & 1) * 64;
    int wn = (wid >> 1) * 32;

    int bm = blockIdx.y * 128;
    int bn = blockIdx.x * 128;

    int lrow = tid >> 2;          // 0..63
    int lc4  = (tid & 3) * 4;

    const float* Ar0 = A  + (long)(bm + lrow) * lda + lc4;
    const float* Ar1 = A  + (long)(bm + lrow + 64) * lda + lc4;
    const float* Br0 = Bm + (long)(bn + lrow) * ldb + lc4;
    const float* Br1 = Bm + (long)(bn + lrow + 64) * ldb + lc4;

    float acc[4][4][4];
#pragma unroll
    for (int i = 0; i < 4; i++)
#pragma unroll
        for (int j = 0; j < 4; j++)
#pragma unroll
            for (int r = 0; r < 4; r++) acc[i][j][r] = 0.0f;

    float4 pa0 = *(const float4*)(Ar0);
    float4 pa1 = *(const float4*)(Ar1);
    float4 pb0 = *(const float4*)(Br0);
    float4 pb1 = *(const float4*)(Br1);

    for (int k0 = 0; k0 < K; k0 += 16) {
        unsigned* da0 = &As[lrow * SK16 + lc4];
        da0[0] = f2tf32(pa0.x); da0[1] = f2tf32(pa0.y);
        da0[2] = f2tf32(pa0.z); da0[3] = f2tf32(pa0.w);
        unsigned* da1 = &As[(lrow + 64) * SK16 + lc4];
        da1[0] = f2tf32(pa1.x); da1[1] = f2tf32(pa1.y);
        da1[2] = f2tf32(pa1.z); da1[3] = f2tf32(pa1.w);
        unsigned* db0 = &Bs[lrow * SK16 + lc4];
        db0[0] = f2tf32(pb0.x); db0[1] = f2tf32(pb0.y);
        db0[2] = f2tf32(pb0.z); db0[3] = f2tf32(pb0.w);
        unsigned* db1 = &Bs[(lrow + 64) * SK16 + lc4];
        db1[0] = f2tf32(pb1.x); db1[1] = f2tf32(pb1.y);
        db1[2] = f2tf32(pb1.z); db1[3] = f2tf32(pb1.w);
        __syncthreads();

        if (k0 + 16 < K) {
            pa0 = *(const float4*)(Ar0 + k0 + 16);
            pa1 = *(const float4*)(Ar1 + k0 + 16);
            pb0 = *(const float4*)(Br0 + k0 + 16);
            pb1 = *(const float4*)(Br1 + k0 + 16);
        }

#pragma unroll
        for (int ks = 0; ks < 2; ks++) {
            int kb = ks * 8;
            unsigned a[4][4], b[4][2];
#pragma unroll
            for (int mf = 0; mf < 4; mf++) {
                int m = wm + mf * 16;
                a[mf][0] = As[(m + g) * SK16 + kb + tg];
                a[mf][1] = As[(m + g + 8) * SK16 + kb + tg];
                a[mf][2] = As[(m + g) * SK16 + kb + tg + 4];
                a[mf][3] = As[(m + g + 8) * SK16 + kb + tg + 4];
            }
#pragma unroll
            for (int nf = 0; nf < 4; nf++) {
                int n = wn + nf * 8;
                b[nf][0] = Bs[(n + g) * SK16 + kb + tg];
                b[nf][1] = Bs[(n + g) * SK16 + kb + tg + 4];
            }
#pragma unroll
            for (int mf = 0; mf < 4; mf++)
#pragma unroll
                for (int nf = 0; nf < 4; nf++)
                    mma_tf32(acc[mf][nf], a[mf], b[nf]);
        }
        __syncthreads();
    }

#pragma unroll
    for (int mf = 0; mf < 4; mf++) {
#pragma unroll
        for (int nf = 0; nf < 4; nf++) {
            int m0 = bm + wm + mf * 16 + g;
            int n0 = bn + wn + nf * 8 + 2 * tg;
            float b0 = bias ? bias[n0] : 0.0f;
            float b1 = bias ? bias[n0 + 1] : 0.0f;
            float* c0 = C + (long)m0 * ldc + n0;
            float* c1 = C + (long)(m0 + 8) * ldc + n0;
            c0[0] = alpha * acc[mf][nf][0] + b0;
            c0[1] = alpha * acc[mf][nf][1] + b1;
            c1[0] = alpha * acc[mf][nf][2] + b0;
            c1[1] = alpha * acc[mf][nf][3] + b1;
        }
    }
}

// =============================================================================
// Fused flash attention with softmax-one, writing normalized attn exactly once.
// grid (1, 16 q-tiles, 32 (b,h)); 256 threads; dynamic smem 179200 B.
// Pass 1: S = QK^T/8 tile-by-tile, online row-max / row-sum (no gmem traffic).
// Pass 2: recompute S, P = exp(S - M) / (1 + sum), STG P, PV mma -> X.
// =============================================================================
#define QS 68    // Qs/Ks stride (floats): conflict-free frag LDS
#define VS 72    // Vs stride
#define PS 132   // Ps stride

__global__ __launch_bounds__(256, 1)
void fattn(const float* __restrict__ Qg, const float* __restrict__ Kg,
           const float* __restrict__ Vg, float* __restrict__ attn,
           float* __restrict__ Xg)
{
    extern __shared__ unsigned smem_u[];
    unsigned* Qs = smem_u;                          // [128][QS]
    unsigned* Ks = Qs + 128 * QS;                   // [128][QS]
    unsigned* Vs = Ks + 128 * QS;                   // [128][VS] (k-row major)
    unsigned* Ps = Vs + 128 * VS;                   // [128][PS]
    float* rmax = (float*)(Ps + 128 * PS);          // [4][128]
    float* rsum = rmax + 4 * 128;                   // [4][128]
    float* mrow = rsum + 4 * 128;                   // [128]
    float* invr = mrow + 128;                       // [128]

    int z = blockIdx.z, b = z >> 4, h = z & 15;
    int bm = blockIdx.y * 128;
    const float* Qz = Qg + ((long)b * TT + bm) * DD + h * DKK;
    const float* Kz = Kg + (long)b * TT * DD + h * DKK;
    const float* Vz = Vg + (long)b * TT * DD + h * DKK;
    float* Az = attn + (long)z * TT * TT + (long)bm * TT;
    float* Xz = Xg + ((long)b * TT + bm) * DD + h * DKK;

    int tid = threadIdx.x, lane = tid & 31, wid = tid >> 5;
    int g = lane >> 2, tg = lane & 3;
    int wm = (wid & 1) * 64, wn = (wid >> 1) * 32;      // QK warp layout (2m x 4n)
    int wm2 = (wid >> 1) * 32, wn2 = (wid & 1) * 32;    // PV warp layout (4m x 2n)
    int wnidx = wid >> 1;

    int lrow = tid >> 4;           // 0..15
    int lc4  = (tid & 15) * 4;     // 0..60

    // ---- load Q tile (128x64) -> Qs tf32 ----
#pragma unroll
    for (int i = 0; i < 8; i++) {
        int row = lrow + i * 16;
        float4 qv = *(const float4*)(Qz + (long)row * DD + lc4);
        uint4 t = { f2tf32(qv.x), f2tf32(qv.y), f2tf32(qv.z), f2tf32(qv.w) };
        *(uint4*)(&Qs[row * QS + lc4]) = t;
    }

    // ================= pass 1: online row max & sum =================
    float4 kb4[8];
#pragma unroll
    for (int i = 0; i < 8; i++)
        kb4[i] = *(const float4*)(Kz + (long)(lrow + i * 16) * DD + lc4);

    float mrun[4][2], srun[4][2];
#pragma unroll
    for (int mf = 0; mf < 4; mf++) {
        mrun[mf][0] = mrun[mf][1] = -1e30f;
        srun[mf][0] = srun[mf][1] = 0.0f;
    }

    for (int kt = 0; kt < 16; kt++) {
        __syncthreads();
#pragma unroll
        for (int i = 0; i < 8; i++) {
            uint4 t = { f2tf32(kb4[i].x), f2tf32(kb4[i].y), f2tf32(kb4[i].z), f2tf32(kb4[i].w) };
            *(uint4*)(&Ks[(lrow + i * 16) * QS + lc4]) = t;
        }
        __syncthreads();
        if (kt < 15) {
#pragma unroll
            for (int i = 0; i < 8; i++)
                kb4[i] = *(const float4*)(Kz + (long)((kt + 1) * 128 + lrow + i * 16) * DD + lc4);
        }

        float acc[4][4][4];
#pragma unroll
        for (int i = 0; i < 4; i++)
#pragma unroll
            for (int j = 0; j < 4; j++)
#pragma unroll
                for (int r = 0; r < 4; r++) acc[i][j][r] = 0.0f;

#pragma unroll
        for (int ks = 0; ks < 8; ks++) {
            int kb = ks * 8;
            unsigned a[4][4], bf[4][2];
#pragma unroll
            for (int mf = 0; mf < 4; mf++) {
                int m = wm + mf * 16;
                a[mf][0] = Qs[(m + g) * QS + kb + tg];
                a[mf][1] = Qs[(m + g + 8) * QS + kb + tg];
                a[mf][2] = Qs[(m + g) * QS + kb + tg + 4];
                a[mf][3] = Qs[(m + g + 8) * QS + kb + tg + 4];
            }
#pragma unroll
            for (int nf = 0; nf < 4; nf++) {
                int n = wn + nf * 8;
                bf[nf][0] = Ks[(n + g) * QS + kb + tg];
                bf[nf][1] = Ks[(n + g) * QS + kb + tg + 4];
            }
#pragma unroll
            for (int mf = 0; mf < 4; mf++)
#pragma unroll
                for (int nf = 0; nf < 4; nf++)
                    mma_tf32(acc[mf][nf], a[mf], bf[nf]);
        }

        // online softmax-one state update (scale 0.125 > 0: max commutes)
#pragma unroll
        for (int mf = 0; mf < 4; mf++) {
#pragma unroll
            for (int i = 0; i < 2; i++) {
                float tm = -1e30f;
#pragma unroll
                for (int nf = 0; nf < 4; nf++)
                    tm = fmaxf(tm, fmaxf(acc[mf][nf][2 * i], acc[mf][nf][2 * i + 1]));
                tm *= 0.125f;
                float mn = fmaxf(mrun[mf][i], tm);
                float add = 0.0f;
#pragma unroll
                for (int nf = 0; nf < 4; nf++) {
                    add += __expf(0.125f * acc[mf][nf][2 * i]     - mn);
                    add += __expf(0.125f * acc[mf][nf][2 * i + 1] - mn);
                }
                srun[mf][i] = srun[mf][i] * __expf(mrun[mf][i] - mn) + add;
                mrun[mf][i] = mn;
            }
        }
    }

    // reduce (m,s) across tg lanes, then across the 4 n-warps via smem
#pragma unroll
    for (int mf = 0; mf < 4; mf++)
#pragma unroll
        for (int i = 0; i < 2; i++) {
            float m = mrun[mf][i], s = srun[mf][i];
#pragma unroll
            for (int sft = 1; sft <= 2; sft <<= 1) {
                float mo = __shfl_xor_sync(0xffffffffu, m, sft);
                float so = __shfl_xor_sync(0xffffffffu, s, sft);
                float M = fmaxf(m, mo);
                s = s * __expf(m - M) + so * __expf(mo - M);
                m = M;
            }
            if (tg == 0) {
                int row = wm + mf * 16 + g + i * 8;
                rmax[wnidx * 128 + row] = m;
                rsum[wnidx * 128 + row] = s;
            }
        }
    __syncthreads();
    if (tid < 128) {
        float m0 = rmax[tid], m1 = rmax[128 + tid], m2 = rmax[256 + tid], m3 = rmax[384 + tid];
        float M = fmaxf(fmaxf(m0, m1), fmaxf(m2, m3));
        float S = rsum[tid] * __expf(m0 - M) + rsum[128 + tid] * __expf(m1 - M)
                + rsum[256 + tid] * __expf(m2 - M) + rsum[384 + tid] * __expf(m3 - M);
        mrow[tid] = M;
        invr[tid] = 1.0f / (1.0f + S);   // softmax-one: +1 in shifted denom
    }
    __syncthreads();

    float mA[4], mB[4], iA[4], iB[4];
#pragma unroll
    for (int mf = 0; mf < 4; mf++) {
        mA[mf] = mrow[wm + mf * 16 + g];     iA[mf] = invr[wm + mf * 16 + g];
        mB[mf] = mrow[wm + mf * 16 + g + 8]; iB[mf] = invr[wm + mf * 16 + g + 8];
    }

    // ================= pass 2: recompute S, emit P, accumulate X =================
    float4 vb4[8];
#pragma unroll
    for (int i = 0; i < 8; i++) {
        kb4[i] = *(const float4*)(Kz + (long)(lrow + i * 16) * DD + lc4);
        vb4[i] = *(const float4*)(Vz + (long)(lrow + i * 16) * DD + lc4);
    }

    float xacc[2][4][4];
#pragma unroll
    for (int i = 0; i < 2; i++)
#pragma unroll
        for (int j = 0; j < 4; j++)
#pragma unroll
            for (int r = 0; r < 4; r++) xacc[i][j][r] = 0.0f;

    for (int kt = 0; kt < 16; kt++) {
        __syncthreads();
#pragma unroll
        for (int i = 0; i < 8; i++) {
            int row = lrow + i * 16;
            uint4 tk = { f2tf32(kb4[i].x), f2tf32(kb4[i].y), f2tf32(kb4[i].z), f2tf32(kb4[i].w) };
            *(uint4*)(&Ks[row * QS + lc4]) = tk;
            uint4 tv = { f2tf32(vb4[i].x), f2tf32(vb4[i].y), f2tf32(vb4[i].z), f2tf32(vb4[i].w) };
            *(uint4*)(&Vs[row * VS + lc4]) = tv;
        }
        __syncthreads();
        if (kt < 15) {
#pragma unroll
            for (int i = 0; i < 8; i++) {
                long off = (long)((kt + 1) * 128 + lrow + i * 16) * DD + lc4;
                kb4[i] = *(const float4*)(Kz + off);
                vb4[i] = *(const float4*)(Vz + off);
            }
        }

        float acc[4][4][4];
#pragma unroll
        for (int i = 0; i < 4; i++)
#pragma unroll
            for (int j = 0; j < 4; j++)
#pragma unroll
                for (int r = 0; r < 4; r++) acc[i][j][r] = 0.0f;

#pragma unroll
        for (int ks = 0; ks < 8; ks++) {
            int kb = ks * 8;
            unsigned a[4][4], bf[4][2];
#pragma unroll
            for (int mf = 0; mf < 4; mf++) {
                int m = wm + mf * 16;
                a[mf][0] = Qs[(m + g) * QS + kb + tg];
                a[mf][1] = Qs[(m + g + 8) * QS + kb + tg];
                a[mf][2] = Qs[(m + g) * QS + kb + tg + 4];
                a[mf][3] = Qs[(m + g + 8) * QS + kb + tg + 4];
            }
#pragma unroll
            for (int nf = 0; nf < 4; nf++) {
                int n = wn + nf * 8;
                bf[nf][0] = Ks[(n + g) * QS + kb + tg];
                bf[nf][1] = Ks[(n + g) * QS + kb + tg + 4];
            }
#pragma unroll
            for (int mf = 0; mf < 4; mf++)
#pragma unroll
                for (int nf = 0; nf < 4; nf++)
                    mma_tf32(acc[mf][nf], a[mf], bf[nf]);
        }

        // P = exp(S - M) * inv ; write attn (only attn gmem traffic) + Ps
#pragma unroll
        for (int mf = 0; mf < 4; mf++) {
#pragma unroll
            for (int nf = 0; nf < 4; nf++) {
                int m0 = wm + mf * 16 + g;
                int n0 = wn + nf * 8 + 2 * tg;
                float e0 = __expf(0.125f * acc[mf][nf][0] - mA[mf]) * iA[mf];
                float e1 = __expf(0.125f * acc[mf][nf][1] - mA[mf]) * iA[mf];
                float e2 = __expf(0.125f * acc[mf][nf][2] - mB[mf]) * iB[mf];
                float e3 = __expf(0.125f * acc[mf][nf][3] - mB[mf]) * iB[mf];
                *(float2*)(Az + (long)m0 * TT + kt * 128 + n0)       = make_float2(e0, e1);
                *(float2*)(Az + (long)(m0 + 8) * TT + kt * 128 + n0) = make_float2(e2, e3);
                uint2 u0 = { f2tf32(e0), f2tf32(e1) };
                uint2 u1 = { f2tf32(e2), f2tf32(e3) };
                *(uint2*)(&Ps[m0 * PS + n0])       = u0;
                *(uint2*)(&Ps[(m0 + 8) * PS + n0]) = u1;
            }
        }
        __syncthreads();

        // X += P @ V  (PV warp layout)
#pragma unroll
        for (int ks = 0; ks < 16; ks++) {
            int kb = ks * 8;
            unsigned a2[2][4], b2[4][2];
#pragma unroll
            for (int mf = 0; mf < 2; mf++) {
                int m = wm2 + mf * 16;
                a2[mf][0] = Ps[(m + g) * PS + kb + tg];
                a2[mf][1] = Ps[(m + g + 8) * PS + kb + tg];
                a2[mf][2] = Ps[(m + g) * PS + kb + tg + 4];
                a2[mf][3] = Ps[(m + g + 8) * PS + kb + tg + 4];
            }
#pragma unroll
            for (int nf = 0; nf < 4; nf++) {
                int n = wn2 + nf * 8;
                b2[nf][0] = Vs[(kb + tg) * VS + n + g];
                b2[nf][1] = Vs[(kb + tg + 4) * VS + n + g];
            }
#pragma unroll
            for (int mf = 0; mf < 2; mf++)
#pragma unroll
                for (int nf = 0; nf < 4; nf++)
                    mma_tf32(xacc[mf][nf], a2[mf], b2[nf]);
        }
    }

    // X epilogue -> [B,T,D] layout
#pragma unroll
    for (int mf = 0; mf < 2; mf++)
#pragma unroll
        for (int nf = 0; nf < 4; nf++) {
            int m0 = wm2 + mf * 16 + g;
            int n0 = wn2 + nf * 8 + 2 * tg;
            *(float2*)(Xz + (long)m0 * DD + n0)       = make_float2(xacc[mf][nf][0], xacc[mf][nf][1]);
            *(float2*)(Xz + (long)(m0 + 8) * DD + n0) = make_float2(xacc[mf][nf][2], xacc[mf][nf][3]);
        }
}

#define FATTN_SMEM ((128 * QS * 2 + 128 * VS + 128 * PS) * 4 + (4 * 128 * 2 + 128 * 2) * 4)

// =============================================================================
// residual + LayerNorm: y = LN(query + o) * gamma + beta ; one block per row
// =============================================================================
__global__ __launch_bounds__(256)
void resid_ln_k(const float* __restrict__ q, const float* __restrict__ o,
                const float* __restrict__ gamma, const float* __restrict__ beta,
                float* __restrict__ out)
{
    __shared__ float redA[8], redB[8];
    __shared__ float s_mu, s_rstd;

    long row = blockIdx.x;
    const float* qp = q + row * DD;
    const float* op = o + row * DD;
    float* yp = out + row * DD;
    int tid = threadIdx.x;

    float4 a = *(const float4*)(qp + tid * 4);
    float4 b = *(const float4*)(op + tid * 4);
    float4 y = make_float4(a.x + b.x, a.y + b.y, a.z + b.z, a.w + b.w);

    float s  = y.x + y.y + y.z + y.w;
    float s2 = y.x * y.x + y.y * y.y + y.z * y.z + y.w * y.w;
#pragma unroll
    for (int sh = 16; sh > 0; sh >>= 1) {
        s  += __shfl_xor_sync(0xffffffffu, s,  sh);
        s2 += __shfl_xor_sync(0xffffffffu, s2, sh);
    }
    if ((tid & 31) == 0) { redA[tid >> 5] = s; redB[tid >> 5] = s2; }
    __syncthreads();
    if (tid < 32) {
        float t  = redA[tid & 7];
        float t2 = redB[tid & 7];
#pragma unroll
        for (int sh = 4; sh > 0; sh >>= 1) {
            t  += __shfl_xor_sync(0xffffffffu, t,  sh);
            t2 += __shfl_xor_sync(0xffffffffu, t2, sh);
        }
        if (tid == 0) {
            float mu  = t / (float)DD;
            float var = t2 / (float)DD - mu * mu;
            s_mu = mu;
            s_rstd = rsqrtf(var + 1e-5f);
        }
    }
    __syncthreads();
    float mu = s_mu, rstd = s_rstd;

    float4 gm = *(const float4*)(gamma + tid * 4);
    float4 be = *(const float4*)(beta + tid * 4);
    float4 r;
    r.x = (y.x - mu) * rstd * gm.x + be.x;
    r.y = (y.y - mu) * rstd * gm.y + be.y;
    r.z = (y.z - mu) * rstd * gm.z + be.z;
    r.w = (y.w - mu) * rstd * gm.w + be.w;
    *(float4*)(yp + tid * 4) = r;
}

// =============================================================================
extern "C" void kernel_launch(void* const* d_in, const int* in_sizes, int n_in,
                              void* d_out, int out_size)
{
    const float* query = (const float*)d_in[0];
    const float* key   = (const float*)d_in[1];
    const float* value = (const float*)d_in[2];
    const float* Wq = (const float*)d_in[3];
    const float* bq = (const float*)d_in[4];
    const float* Wk = (const float*)d_in[5];
    const float* bk = (const float*)d_in[6];
    const float* Wv = (const float*)d_in[7];
    const float* bv = (const float*)d_in[8];
    const float* Wo = (const float*)d_in[9];
    const float* bo = (const float*)d_in[10];
    const float* gamma = (const float*)d_in[11];
    const float* beta  = (const float*)d_in[12];

    float* out = (float*)d_out;

    float *q, *k, *v, *x, *o, *attn_scr;
    cudaGetSymbolAddress((void**)&q, g_q);
    cudaGetSymbolAddress((void**)&k, g_k);
    cudaGetSymbolAddress((void**)&v, g_v);
    cudaGetSymbolAddress((void**)&x, g_x);
    cudaGetSymbolAddress((void**)&o, g_o);
    cudaGetSymbolAddress((void**)&attn_scr, g_attn_scratch);

    const long y_elems    = (long)BB * TT * DD;
    const long attn_elems = (long)BB * HH * TT * TT;
    float* y_out = out;
    float* attn  = ((long)out_size >= y_elems + attn_elems) ? (out + y_elems)
                                                            : attn_scr;

    static int smem_set = 0;
    if (!smem_set) {
        cudaFuncSetAttribute(fattn, cudaFuncAttributeMaxDynamicSharedMemorySize,
                             FATTN_SMEM);
        smem_set = 1;
    }

    dim3 tpb(256);

    // QKV projections: [4096,1024] @ W^T + b  (tensor cores, tf32)
    dim3 gproj(DD / 128, BT / 128, 1);
    mma_nt<<<gproj, tpb>>>(query, DD, Wq, DD, q, DD, bq, DD, 1.0f);
    mma_nt<<<gproj, tpb>>>(key,   DD, Wk, DD, k, DD, bk, DD, 1.0f);
    mma_nt<<<gproj, tpb>>>(value, DD, Wv, DD, v, DD, bv, DD, 1.0f);

    // fused scores + softmax-one + attn write + attn@V
    dim3 gf(1, TT / 128, BB * HH);
    fattn<<<gf, tpb, FATTN_SMEM>>>(q, k, v, attn, x);

    // output projection
    mma_nt<<<gproj, tpb>>>(x, DD, Wo, DD, o, DD, bo, DD, 1.0f);

    // residual + LayerNorm -> y
    resid_ln_k<<<BT, tpb>>>(query, o, gamma, beta, y_out);
}